// round 6
// baseline (speedup 1.0000x reference)
#include <cuda_runtime.h>

#define N_SRC  10000
#define N_DST  40000
#define NE     1280000
#define IN_DIM 128
#define D      64
#define FEAT   64
#define O_DIM  300

#define EL_TILES (NE / 128)   // 10000
#define EL_GRID  296

typedef unsigned long long u64;
typedef unsigned int u32;

// ---- scratch (static __device__ — no allocations anywhere) ----
__device__ __align__(16) float g_zsrc[N_SRC * D];
__device__ __align__(16) float g_zdst[N_DST * D];
__device__ float g_e2[NE];                          // logits in CSR order
__device__ int   g_srcperm[NE];                     // esrc in CSR order
__device__ __align__(16) float g_WT[FEAT * D];      // W_feat transposed [n][k]
__device__ int g_hist[N_DST];
__device__ int g_cursor[N_DST];
__device__ int g_rowstart[N_DST + 1];
__device__ int g_csr[NE];

// ---- helpers ----
__device__ __forceinline__ u64 pack2(float lo, float hi) {
    u64 r; asm("mov.b64 %0, {%1, %2};" : "=l"(r) : "f"(lo), "f"(hi)); return r;
}
__device__ __forceinline__ u64 fma2(u64 a, u64 b, u64 c) {
    u64 d; asm("fma.rn.f32x2 %0, %1, %2, %3;" : "=l"(d) : "l"(a), "l"(b), "l"(c)); return d;
}
__device__ __forceinline__ u32 cvt_tf32(float x) {
    u32 u; asm("cvt.rna.tf32.f32 %0, %1;" : "=r"(u) : "f"(x)); return u;
}
__device__ __forceinline__ uint4 cvt4(float4 v) {
    uint4 w; w.x = cvt_tf32(v.x); w.y = cvt_tf32(v.y);
    w.z = cvt_tf32(v.z); w.w = cvt_tf32(v.w); return w;
}
__device__ __forceinline__ void mma_tf32(float c[4], u32 a0, u32 a1, u32 a2, u32 a3,
                                         u32 b0, u32 b1) {
    asm("mma.sync.aligned.m16n8k8.row.col.f32.tf32.tf32.f32 "
        "{%0,%1,%2,%3}, {%4,%5,%6,%7}, {%8,%9}, {%0,%1,%2,%3};"
        : "+f"(c[0]), "+f"(c[1]), "+f"(c[2]), "+f"(c[3])
        : "r"(a0), "r"(a1), "r"(a2), "r"(a3), "r"(b0), "r"(b1));
}
__device__ __forceinline__ void ldsm4(u32& r0, u32& r1, u32& r2, u32& r3, u32 addr) {
    asm volatile("ldmatrix.sync.aligned.m8n8.x4.shared.b16 {%0,%1,%2,%3}, [%4];"
                 : "=r"(r0), "=r"(r1), "=r"(r2), "=r"(r3) : "r"(addr));
}
__device__ __forceinline__ void cpa16(u32 saddr, const void* g) {
    asm volatile("cp.async.ca.shared.global [%0], [%1], 16;" :: "r"(saddr), "l"(g));
}
#define CP_COMMIT() asm volatile("cp.async.commit_group;" ::: "memory")
#define CP_WAIT(n)  asm volatile("cp.async.wait_group %0;" :: "n"(n) : "memory")

// ============================================================================
// CSR build
// ============================================================================
__global__ void prep_kernel(const float* __restrict__ W_feat) {
    int i = blockIdx.x * 256 + threadIdx.x;
    if (i < N_DST) { g_hist[i] = 0; g_cursor[i] = 0; }
    if (i < FEAT * D) g_WT[(i & 63) * 64 + (i >> 6)] = W_feat[i];
}

__global__ void __launch_bounds__(256) hist_kernel(const int* __restrict__ edst) {
    int i4 = blockIdx.x * 256 + threadIdx.x;           // NE/4 = 320000 exact
    int4 d = reinterpret_cast<const int4*>(edst)[i4];
    atomicAdd(&g_hist[d.x], 1);
    atomicAdd(&g_hist[d.y], 1);
    atomicAdd(&g_hist[d.z], 1);
    atomicAdd(&g_hist[d.w], 1);
}

__global__ void __launch_bounds__(1024) scan_kernel() {
    __shared__ int part[1024];
    const int t = threadIdx.x;
    const int CH = 40;
    int own = 0;
    for (int j = 0; j < CH; j++) {
        int idx = t * CH + j;
        if (idx < N_DST) own += g_hist[idx];
    }
    part[t] = own;
    __syncthreads();
    for (int off = 1; off < 1024; off <<= 1) {
        int v = (t >= off) ? part[t - off] : 0;
        __syncthreads();
        part[t] += v;
        __syncthreads();
    }
    int base = part[t] - own;
    for (int j = 0; j < CH; j++) {
        int idx = t * CH + j;
        if (idx < N_DST) { g_rowstart[idx] = base; base += g_hist[idx]; }
    }
    if (t == 1023) g_rowstart[N_DST] = part[1023];
}

__global__ void __launch_bounds__(256) fill_kernel(const int* __restrict__ edst) {
    int i4 = blockIdx.x * 256 + threadIdx.x;
    int4 d = reinterpret_cast<const int4*>(edst)[i4];
    int base = i4 * 4;
    int p0 = atomicAdd(&g_cursor[d.x], 1);
    int p1 = atomicAdd(&g_cursor[d.y], 1);
    int p2 = atomicAdd(&g_cursor[d.z], 1);
    int p3 = atomicAdd(&g_cursor[d.w], 1);
    g_csr[g_rowstart[d.x] + p0] = base;
    g_csr[g_rowstart[d.y] + p1] = base + 1;
    g_csr[g_rowstart[d.z] + p2] = base + 2;
    g_csr[g_rowstart[d.w] + p3] = base + 3;
}

// ============================================================================
// K1: z_src = h @ W_fc, full fp32 (feeds output directly).
// ============================================================================
__global__ void __launch_bounds__(128) rowgemm_zsrc(const float* __restrict__ A,
                                                    const float* __restrict__ B,
                                                    int M, int K) {
    __shared__ __align__(16) float As[128][33];
    __shared__ __align__(16) float Bs[32][64];
    int row = blockIdx.x * 128 + threadIdx.x;
    u64 acc[32];
#pragma unroll
    for (int i = 0; i < 32; i++) acc[i] = 0ull;

    for (int k0 = 0; k0 < K; k0 += 32) {
        __syncthreads();
        for (int idx = threadIdx.x; idx < 128 * 32; idx += 128) {
            int r = idx >> 5, c = idx & 31;
            int gr = blockIdx.x * 128 + r, gc = k0 + c;
            As[r][c] = (gr < M && gc < K) ? A[gr * K + gc] : 0.f;
        }
        for (int idx = threadIdx.x; idx < 32 * 64; idx += 128) {
            int r = idx >> 6, c = idx & 63;
            int gk = k0 + r;
            Bs[r][c] = (gk < K) ? B[gk * 64 + c] : 0.f;
        }
        __syncthreads();
#pragma unroll 4
        for (int kk = 0; kk < 32; kk++) {
            float t = As[threadIdx.x][kk];
            u64 tt = pack2(t, t);
            const ulonglong2* br = reinterpret_cast<const ulonglong2*>(&Bs[kk][0]);
#pragma unroll
            for (int i = 0; i < 16; i++) {
                ulonglong2 w = br[i];
                acc[2 * i]     = fma2(tt, w.x, acc[2 * i]);
                acc[2 * i + 1] = fma2(tt, w.y, acc[2 * i + 1]);
            }
        }
    }
    if (row < M) {
        u64* out = reinterpret_cast<u64*>(g_zsrc + row * D);
#pragma unroll
        for (int i = 0; i < 32; i++) out[i] = acc[i];
    }
}

// ============================================================================
// K2: z_dst = o @ W_fc1 via tf32 mma (logits-only precision).
// ============================================================================
__global__ void __launch_bounds__(256) gemm_tf32_zdst(const float* __restrict__ A,
                                                      const float* __restrict__ B,
                                                      int M, int K) {
    __shared__ u32 Ts[64][68];
    __shared__ u32 Bs[64][72];

    const int tid  = threadIdx.x;
    const int warp = tid >> 5, lane = tid & 31;
    const int g = lane >> 2, tg = lane & 3;
    const int eg = warp >> 1, nh = warp & 1;
    const int rbase = blockIdx.x * 64;
    const int Kf4 = K >> 2;

    float acc[4][4];
#pragma unroll
    for (int nt = 0; nt < 4; nt++)
#pragma unroll
        for (int j = 0; j < 4; j++) acc[nt][j] = 0.f;

    const int KO = (K + 63) / 64;
    for (int ko = 0; ko < KO; ko++) {
        __syncthreads();
#pragma unroll
        for (int j = 0; j < 4; j++) {
            int idx = tid + j * 256;
            int r = idx >> 4, c4 = idx & 15;
            int gr = rbase + r, gf4 = ko * 16 + c4;
            float4 v = make_float4(0.f, 0.f, 0.f, 0.f);
            if (gr < M && gf4 < Kf4)
                v = reinterpret_cast<const float4*>(A + (u64)gr * K)[gf4];
            *reinterpret_cast<uint4*>(&Ts[r][c4 * 4]) = cvt4(v);
        }
#pragma unroll
        for (int j = 0; j < 4; j++) {
            int idx = tid + j * 256;
            int r = idx >> 4, c4 = idx & 15;
            int gk = ko * 64 + r;
            float4 v = make_float4(0.f, 0.f, 0.f, 0.f);
            if (gk < K)
                v = reinterpret_cast<const float4*>(B + gk * 64)[c4];
            *reinterpret_cast<uint4*>(&Bs[r][c4 * 4]) = cvt4(v);
        }
        __syncthreads();

        const int m0 = eg * 16;
#pragma unroll
        for (int kc = 0; kc < 8; kc++) {
            int k = kc * 8;
            u32 a0 = Ts[m0 + g][k + tg];
            u32 a1 = Ts[m0 + 8 + g][k + tg];
            u32 a2 = Ts[m0 + g][k + tg + 4];
            u32 a3 = Ts[m0 + 8 + g][k + tg + 4];
#pragma unroll
            for (int nt = 0; nt < 4; nt++) {
                int n0 = nh * 32 + nt * 8 + g;
                u32 b0 = Bs[k + tg][n0];
                u32 b1 = Bs[k + tg + 4][n0];
                mma_tf32(acc[nt], a0, a1, a2, a3, b0, b1);
            }
        }
    }

#pragma unroll
    for (int rh = 0; rh < 2; rh++) {
        int row = rbase + eg * 16 + rh * 8 + g;
        if (row < M) {
#pragma unroll
            for (int nt = 0; nt < 4; nt++) {
                int col = nh * 32 + nt * 8 + 2 * tg;
                float2 v = make_float2(acc[nt][rh * 2], acc[nt][rh * 2 + 1]);
                *reinterpret_cast<float2*>(g_zdst + row * D + col) = v;
            }
        }
    }
}

// ============================================================================
// K3: persistent edge-logits in CSR order. 296 blocks grid-stride over 10000
// tiles of 128 edges. W_feat^T staged once/block; tfidf tile t+1 via cp.async
// (raw fp32 bits as tf32 — HW truncates low mantissa) overlapped with tile t
// compute. Double-buffered A.  smem = 2*128*68 + 64*68 u32 = 87040 B.
// ============================================================================
__global__ void __launch_bounds__(256) edge_logits_tc(const float* __restrict__ tfidf,
                                                      const float* __restrict__ b_feat,
                                                      const float* __restrict__ W_attn,
                                                      const int* __restrict__ esrc,
                                                      const int* __restrict__ edst) {
    extern __shared__ u32 smbuf[];
    u32 (*A0)[68] = reinterpret_cast<u32(*)[68]>(smbuf);
    u32 (*A1)[68] = reinterpret_cast<u32(*)[68]>(smbuf + 128 * 68);
    u32 (*Bs)[68] = reinterpret_cast<u32(*)[68]>(smbuf + 2 * 128 * 68);

    const int tid  = threadIdx.x;
    const int warp = tid >> 5, lane = tid & 31;
    const int g = lane >> 2, tg = lane & 3;
    const int rr = tid >> 4, c4 = tid & 15;   // staging: row part / 16B col part

    // stage W_feat^T once (cp.async, raw fp32)
#pragma unroll
    for (int j = 0; j < 4; j++) {
        int idx = tid + j * 256;
        int r = idx >> 4, cc = idx & 15;
        cpa16((u32)__cvta_generic_to_shared(&Bs[r][cc * 4]), g_WT + r * 64 + cc * 4);
    }

    float2 bf[8], wa[8];
#pragma unroll
    for (int nt = 0; nt < 8; nt++) {
        int col = nt * 8 + 2 * tg;
        bf[nt] = *reinterpret_cast<const float2*>(b_feat + col);
        wa[nt] = *reinterpret_cast<const float2*>(W_attn + col);
    }

    const int m0 = warp * 16;
    const int q = lane >> 3, r8 = lane & 7;
    const u32 aOff = ((m0 + ((q & 1) << 3) + r8) * 68 + (((q >> 1) << 2))) * 4;
    const u32 a0Base = (u32)__cvta_generic_to_shared(A0) + aOff;
    const u32 a1Base = (u32)__cvta_generic_to_shared(A1) + aOff;
    const u32 bBase  = (u32)__cvta_generic_to_shared(&Bs[((q >> 1) << 3) + r8][(q & 1) << 2]);
    const u32 GSTRIDE = 16 * 68 * 4;

    // issue first tile into A0
    int t = blockIdx.x;
    {
        u32 dst = (u32)__cvta_generic_to_shared(&A0[0][0]) + (rr * 68 + c4 * 4) * 4;
#pragma unroll
        for (int j = 0; j < 8; j++) {
            int e = g_csr[t * 128 + rr + j * 16];
            cpa16(dst + j * 16 * 68 * 4, tfidf + (u64)e * FEAT + c4 * 4);
        }
    }
    CP_COMMIT();

    int parity = 0;
    for (; t < EL_TILES; t += EL_GRID) {
        int tn = t + EL_GRID;
        if (tn < EL_TILES) {
            u32 dst = (parity ? (u32)__cvta_generic_to_shared(&A0[0][0])
                              : (u32)__cvta_generic_to_shared(&A1[0][0]))
                      + (rr * 68 + c4 * 4) * 4;
#pragma unroll
            for (int j = 0; j < 8; j++) {
                int e = g_csr[tn * 128 + rr + j * 16];
                cpa16(dst + j * 16 * 68 * 4, tfidf + (u64)e * FEAT + c4 * 4);
            }
            CP_COMMIT();
            CP_WAIT(1);
        } else {
            CP_WAIT(0);
        }
        __syncthreads();

        const u32 aBase = parity ? a1Base : a0Base;
        float acc[8][4];
#pragma unroll
        for (int nt = 0; nt < 8; nt++)
#pragma unroll
            for (int j = 0; j < 4; j++) acc[nt][j] = 0.f;

#pragma unroll
        for (int kc = 0; kc < 8; kc++) {
            u32 ko = kc * 32;
            u32 a0, a1, a2, a3;
            ldsm4(a0, a1, a2, a3, aBase + ko);
#pragma unroll
            for (int G = 0; G < 4; G++) {
                u32 b0, b1, b2, b3;
                ldsm4(b0, b1, b2, b3, bBase + G * GSTRIDE + ko);
                mma_tf32(acc[2 * G],     a0, a1, a2, a3, b0, b1);
                mma_tf32(acc[2 * G + 1], a0, a1, a2, a3, b2, b3);
            }
        }

        // fused epilogue
        const int pbase = t * 128;
#pragma unroll
        for (int rh = 0; rh < 2; rh++) {
            int rl = m0 + rh * 8 + g;
            int pos = pbase + rl;
            int e = g_csr[pos];
            int s = esrc[e], d = edst[e];
            const float* zsp = g_zsrc + s * D;
            const float* zdp = g_zdst + d * D;
            float p = 0.f;
#pragma unroll
            for (int nt = 0; nt < 8; nt++) {
                int col = nt * 8 + 2 * tg;
                float2 zs = *reinterpret_cast<const float2*>(zsp + col);
                float2 zd = *reinterpret_cast<const float2*>(zdp + col);
                float x0 = acc[nt][rh * 2]     + zs.x + zd.x + bf[nt].x;
                float x1 = acc[nt][rh * 2 + 1] + zs.y + zd.y + bf[nt].y;
                p += fmaxf(x0, 0.01f * x0) * wa[nt].x
                   + fmaxf(x1, 0.01f * x1) * wa[nt].y;
            }
            p += __shfl_xor_sync(0xffffffffu, p, 1);
            p += __shfl_xor_sync(0xffffffffu, p, 2);
            if (tg == 0) { g_e2[pos] = p; g_srcperm[pos] = s; }
        }
        __syncthreads();
        parity ^= 1;
    }
}

// ============================================================================
// K4: pull aggregation, streaming. One warp per dst node.
// ============================================================================
__global__ void __launch_bounds__(256) gather_out(float* __restrict__ out) {
    int d = blockIdx.x * 8 + (threadIdx.x >> 5);
    if (d >= N_DST) return;
    const int lane = threadIdx.x & 31;
    const int beg = g_rowstart[d], end = g_rowstart[d + 1];

    float m = -3.4e38f;
    for (int i = beg + lane; i < end; i += 32)
        m = fmaxf(m, g_e2[i]);
    m = fmaxf(m, __shfl_xor_sync(0xffffffffu, m, 16));
    m = fmaxf(m, __shfl_xor_sync(0xffffffffu, m, 8));
    m = fmaxf(m, __shfl_xor_sync(0xffffffffu, m, 4));
    m = fmaxf(m, __shfl_xor_sync(0xffffffffu, m, 2));
    m = fmaxf(m, __shfl_xor_sync(0xffffffffu, m, 1));

    float acc0 = 0.f, acc1 = 0.f, den = 0.f;
    for (int i = beg; i < end; i++) {
        float w = __expf(g_e2[i] - m);
        int s = g_srcperm[i];
        float2 z = *reinterpret_cast<const float2*>(g_zsrc + s * D + lane * 2);
        acc0 += w * z.x;
        acc1 += w * z.y;
        den  += w;
    }
    float inv = 1.f / fmaxf(den, 1e-9f);
    *reinterpret_cast<float2*>(out + (u64)d * D + lane * 2) =
        make_float2(acc0 * inv, acc1 * inv);
}

// ============================================================================
extern "C" void kernel_launch(void* const* d_in, const int* in_sizes, int n_in,
                              void* d_out, int out_size) {
    const float* h      = (const float*)d_in[0];
    const float* o      = (const float*)d_in[1];
    const float* tfidf  = (const float*)d_in[2];
    const float* W_fc   = (const float*)d_in[3];
    const float* W_fc1  = (const float*)d_in[4];
    const float* W_feat = (const float*)d_in[5];
    const float* b_feat = (const float*)d_in[6];
    const float* W_attn = (const float*)d_in[7];
    const int*   esrc   = (const int*)d_in[8];
    const int*   edst   = (const int*)d_in[9];
    float* out = (float*)d_out;

    const int EL_SMEM = (2 * 128 * 68 + 64 * 68) * 4;  // 87040 B
    cudaFuncSetAttribute(edge_logits_tc,
                         cudaFuncAttributeMaxDynamicSharedMemorySize, EL_SMEM);

    prep_kernel<<<(N_DST + 255) / 256, 256>>>(W_feat);
    hist_kernel<<<NE / 1024, 256>>>(edst);
    scan_kernel<<<1, 1024>>>();
    fill_kernel<<<NE / 1024, 256>>>(edst);
    rowgemm_zsrc<<<(N_SRC + 127) / 128, 128>>>(h, W_fc, N_SRC, IN_DIM);
    gemm_tf32_zdst<<<(N_DST + 63) / 64, 256>>>(o, W_fc1, N_DST, O_DIM);
    edge_logits_tc<<<EL_GRID, 256, EL_SMEM>>>(tfidf, b_feat, W_attn, esrc, edst);
    gather_out<<<(N_DST + 7) / 8, 256>>>(out);
}